// round 4
// baseline (speedup 1.0000x reference)
#include <cuda_runtime.h>
#include <math.h>

#define B 96
#define D 512

// ---------------- device scratch (no allocations allowed) ----------------
__device__ float g_dist[B * B];   // pairwise euclidean distances
__device__ int   g_y[B];          // decoded identities
__device__ float g_trip[B];      // per-row triplet loss
__device__ int   g_pos[B];       // hardest-positive index per row
__device__ int   g_neg[B];       // hardest-negative index per row
__device__ float g_ipart[B];     // per-a sum over l of inter[a,l]

// ---------------------------------------------------------------------------
// Kernel 1: pairwise distances. grid (96, 3), block 1024.
// Block (i, jb): 32 warps, warp w computes d[i][jb*32 + w] as a 512-elem
// sum of squared diffs (float4 loads, row i staged in shared).
// Block (0,0) additionally decodes idtys (int32-vs-int64 autodetect) into g_y.
// ---------------------------------------------------------------------------
__global__ __launch_bounds__(1024, 1)
void k_dist(const float* __restrict__ embs, const int* __restrict__ raw_idtys) {
    __shared__ float4 srow[D / 4];   // row i, 2 KB
    __shared__ int s_bad;

    const int i   = blockIdx.x;
    const int jb  = blockIdx.y;
    const int tid = threadIdx.x;

    if (tid < D / 4)
        srow[tid] = ((const float4*)(embs + (size_t)i * D))[tid];
    __syncthreads();

    const int w    = tid >> 5;
    const int lane = tid & 31;
    const int j    = jb * 32 + w;

    const float4* rj = (const float4*)(embs + (size_t)j * D);
    float s = 0.0f;
#pragma unroll
    for (int q = 0; q < 4; q++) {
        float4 a = srow[lane + 32 * q];
        float4 b = rj[lane + 32 * q];
        float d0 = a.x - b.x, d1 = a.y - b.y, d2 = a.z - b.z, d3 = a.w - b.w;
        s += d0 * d0 + d1 * d1 + d2 * d2 + d3 * d3;
    }
#pragma unroll
    for (int o = 16; o; o >>= 1) s += __shfl_down_sync(0xffffffffu, s, o);

    if (lane == 0) {
        // match reference zero-handling: d==0 -> 0, else sqrt
        float dres = (i == j || s <= 0.0f) ? 0.0f : sqrtf(s);
        g_dist[i * B + j] = dres;
    }

    // ---- identity decode, done once by block (0,0) ----
    if (i == 0 && jb == 0) {
        if (tid == 0) s_bad = 0;
        __syncthreads();
        // int64-LE layout looks like pairs (value<16, 0) in an int32 view.
        // Only the first 96 int32s (384B) are read here -> safe in both layouts.
        if (tid < 48) {
            int lo = raw_idtys[2 * tid];
            int hi = raw_idtys[2 * tid + 1];
            if (hi != 0 || (unsigned)lo >= 16u) s_bad = 1;  // benign race, same value
        }
        __syncthreads();
        if (tid < B)
            g_y[tid] = s_bad ? raw_idtys[tid] : raw_idtys[2 * tid];
    }
}

// ---------------------------------------------------------------------------
// Kernel 2: batch-hard mining. grid 96, block 32 (one warp per row).
// Replicates jnp.argmax/argmin first-occurrence tie-breaking exactly.
// ---------------------------------------------------------------------------
__global__ void k_mine() {
    const int i    = blockIdx.x;
    const int lane = threadIdx.x;
    const int yi   = g_y[i];

    float dv[3];
    int   yv[3];
#pragma unroll
    for (int q = 0; q < 3; q++) {
        int j = lane + 32 * q;
        dv[q] = g_dist[i * B + j];
        yv[q] = g_y[j];
    }

    // row max (unmasked) -- needed for an_dist offset
    float maxd = fmaxf(fmaxf(dv[0], dv[1]), dv[2]);
#pragma unroll
    for (int o = 16; o; o >>= 1)
        maxd = fmaxf(maxd, __shfl_xor_sync(0xffffffffu, maxd, o));

    // hardest positive: argmax over mask_ap * d (zeros elsewhere), first occurrence
    float pbest = -1.0f; int pidx = 1 << 20;
#pragma unroll
    for (int q = 0; q < 3; q++) {
        int j = lane + 32 * q;
        float apv = (j != i && yv[q] == yi) ? dv[q] : 0.0f;
        if (apv > pbest) { pbest = apv; pidx = j; }   // strict > keeps smallest j per lane
    }
#pragma unroll
    for (int o = 16; o; o >>= 1) {
        float ov = __shfl_xor_sync(0xffffffffu, pbest, o);
        int   oi = __shfl_xor_sync(0xffffffffu, pidx, o);
        if (ov > pbest || (ov == pbest && oi < pidx)) { pbest = ov; pidx = oi; }
    }

    // hardest negative: argmin over d + maxd*(1-mask_an), first occurrence
    float nbest = 3.4e38f; int nidx = 1 << 20;
#pragma unroll
    for (int q = 0; q < 3; q++) {
        int j = lane + 32 * q;
        float anv = (yv[q] != yi) ? dv[q] : dv[q] + maxd;
        if (anv < nbest) { nbest = anv; nidx = j; }
    }
#pragma unroll
    for (int o = 16; o; o >>= 1) {
        float ov = __shfl_xor_sync(0xffffffffu, nbest, o);
        int   oi = __shfl_xor_sync(0xffffffffu, nidx, o);
        if (ov < nbest || (ov == nbest && oi < nidx)) { nbest = ov; nidx = oi; }
    }

    if (lane == 0) {
        g_trip[i] = fmaxf(pbest - nbest + 0.2f, 0.0f);
        g_pos[i]  = pidx;
        g_neg[i]  = nidx;
    }
}

// ---------------------------------------------------------------------------
// Kernel 3: inter-class term, factorized from O(B^2) per a to O(B):
//   inter[a,l] = lmask(l) * relu(M_a - d[n_a,l] + 0.1)
//   M_a = max_{b != p_a, y_b == y_{p_a}} d[b, p_a]
//   lmask(l) = (y_p != y_n) & (y_p != y_l) & (y_n != y_l), empty-b -> 0
// grid 96 (a), block 32. Writes g_ipart[a] = sum_l inter[a,l].
// ---------------------------------------------------------------------------
__global__ void k_inter() {
    const int a    = blockIdx.x;
    const int lane = threadIdx.x;
    const int p = g_pos[a], n = g_neg[a];
    const int yp = g_y[p], yn = g_y[n];

    float M = -1.0f;   // sentinel: stays -1 iff no valid b
#pragma unroll
    for (int q = 0; q < 3; q++) {
        int b = lane + 32 * q;
        if (b != p && g_y[b] == yp) M = fmaxf(M, g_dist[b * B + p]);
    }
#pragma unroll
    for (int o = 16; o; o >>= 1)
        M = fmaxf(M, __shfl_xor_sync(0xffffffffu, M, o));

    float s = 0.0f;
    if (M >= 0.0f && yp != yn) {
#pragma unroll
        for (int q = 0; q < 3; q++) {
            int l  = lane + 32 * q;
            int yl = g_y[l];
            if (yl != yp && yl != yn)
                s += fmaxf(M - g_dist[n * B + l] + 0.1f, 0.0f);
        }
    }
#pragma unroll
    for (int o = 16; o; o >>= 1) s += __shfl_xor_sync(0xffffffffu, s, o);

    if (lane == 0) g_ipart[a] = s;
}

// ---------------------------------------------------------------------------
// Kernel 4: final reduce. mean(trip) + mean_{a,l}(inter). 1 block, 96 threads.
// Deterministic (fixed-order serial sum over 96 shared values).
// ---------------------------------------------------------------------------
__global__ void k_final(float* __restrict__ out) {
    __shared__ float sh[B];
    const int t = threadIdx.x;
    sh[t] = g_trip[t] * (1.0f / B) + g_ipart[t] * (1.0f / (B * (float)B));
    __syncthreads();
    if (t == 0) {
        float acc = 0.0f;
        for (int k = 0; k < B; k++) acc += sh[k];
        out[0] = acc;
    }
}

// ---------------------------------------------------------------------------
extern "C" void kernel_launch(void* const* d_in, const int* in_sizes, int n_in,
                              void* d_out, int out_size) {
    (void)in_sizes; (void)n_in; (void)out_size;
    const float* embs = (const float*)d_in[0];
    const int*   idt  = (const int*)d_in[1];   // int32 view; layout autodetected
    float*       out  = (float*)d_out;

    k_dist<<<dim3(B, 3), 1024>>>(embs, idt);
    k_mine<<<B, 32>>>();
    k_inter<<<B, 32>>>();
    k_final<<<1, B>>>(out);
}